// round 14
// baseline (speedup 1.0000x reference)
#include <cuda_runtime.h>
#include <cuda_fp16.h>
#include <cstdint>

#define EMBED 512
#define NB 8
#define NS 2048
#define M_TOTAL (NB * NS)   // 16384 rows

// attn output in (b, h, s, d) contiguous layout == the reference's buggy
// reshape. Stored as fp16 (10-bit mantissa == tf32) for the fp16 GEMM.
__device__ __half g_scratch[M_TOTAL * EMBED];  // 16 MB static device scratch
__device__ __half g_Whf[EMBED * EMBED];        // fp16-rounded W (0.5 MB)

// 1/sqrt(8) * log2(e)
#define SCALE_F (0.35355339059327373f * 1.4426950408889634f)

// ---------------------------------------------------------------------------
// helpers
// ---------------------------------------------------------------------------
__device__ __forceinline__ float ex2f(float a) {
    float r;
    asm("ex2.approx.ftz.f32 %0, %1;" : "=f"(r) : "f"(a));
    return r;
}
__device__ __forceinline__ uint32_t cvt_f16x2(float hi, float lo) {
    uint32_t r;
    asm("cvt.rn.f16x2.f32 %0, %1, %2;" : "=r"(r) : "f"(hi), "f"(lo));
    return r;
}
__device__ __forceinline__ uint32_t smem_u32(const void* p) {
    return (uint32_t)__cvta_generic_to_shared(p);
}

__device__ __forceinline__ void cp_async16(uint32_t dst, const void* src) {
    asm volatile("cp.async.cg.shared.global [%0], [%1], 16;" :: "r"(dst), "l"(src));
}
#define CP_COMMIT() asm volatile("cp.async.commit_group;")
#define CP_WAIT(n)  asm volatile("cp.async.wait_group %0;" :: "n"(n))

__device__ __forceinline__ void ldsm4(uint32_t* r, uint32_t addr) {
    asm volatile("ldmatrix.sync.aligned.m8n8.x4.shared.b16 {%0,%1,%2,%3}, [%4];"
                 : "=r"(r[0]), "=r"(r[1]), "=r"(r[2]), "=r"(r[3]) : "r"(addr));
}
__device__ __forceinline__ void ldsm4t(uint32_t* r, uint32_t addr) {
    asm volatile("ldmatrix.sync.aligned.m8n8.x4.trans.shared.b16 {%0,%1,%2,%3}, [%4];"
                 : "=r"(r[0]), "=r"(r[1]), "=r"(r[2]), "=r"(r[3]) : "r"(addr));
}

__device__ __forceinline__ void mma_k8(float* c, const uint32_t* a, uint32_t b) {
    asm volatile(
        "mma.sync.aligned.m16n8k8.row.col.f32.f16.f16.f32 "
        "{%0,%1,%2,%3}, {%4,%5}, {%6}, {%0,%1,%2,%3};\n"
        : "+f"(c[0]), "+f"(c[1]), "+f"(c[2]), "+f"(c[3])
        : "r"(a[0]), "r"(a[1]), "r"(b));
}
__device__ __forceinline__ void mma16(float* c, const uint32_t* a, const uint32_t* b) {
    asm volatile(
        "mma.sync.aligned.m16n8k16.row.col.f32.f16.f16.f32 "
        "{%0,%1,%2,%3}, {%4,%5,%6,%7}, {%8,%9}, {%0,%1,%2,%3};\n"
        : "+f"(c[0]), "+f"(c[1]), "+f"(c[2]), "+f"(c[3])
        : "r"(a[0]), "r"(a[1]), "r"(a[2]), "r"(a[3]), "r"(b[0]), "r"(b[1]));
}

// ---------------------------------------------------------------------------
// Kernel 1: warp-per-token tensor-core attention (unchanged from R8/R9).
// ---------------------------------------------------------------------------
__global__ __launch_bounds__(256) void attn_kernel(
    const float* __restrict__ x, const float* __restrict__ theta,
    const float* __restrict__ W)
{
    __shared__ __align__(16) __half Pb[8 * 512];   // per-warp P   (64x8)
    __shared__ __align__(16) __half Psb[8 * 512];  // per-warp SC*P
    __shared__ float th[8];
    int tid = threadIdx.x;

    // Fold W fp16-rounding into the first 256 blocks (65536 float4s total).
    if (blockIdx.x < 256) {
        int i = blockIdx.x * 256 + tid;
        float4 v = ((const float4*)W)[i];
        __half2 h0 = __floats2half2_rn(v.x, v.y);
        __half2 h1 = __floats2half2_rn(v.z, v.w);
        uint2 u;
        u.x = *(uint32_t*)&h0;
        u.y = *(uint32_t*)&h1;
        ((uint2*)g_Whf)[i] = u;
    }

    if (tid < 8) th[tid] = theta[tid];
    __syncthreads();

    int w = tid >> 5, lane = tid & 31;
    int token = blockIdx.x * 8 + w;
    const float* xt = x + (size_t)token * 512;
    __half* P  = Pb  + w * 512;
    __half* Ps = Psb + w * 512;

#pragma unroll
    for (int rr = 0; rr < 2; rr++) {
        int row = lane + rr * 32;
        float4 v0 = *(const float4*)(xt + row * 8);
        float4 v1 = *(const float4*)(xt + row * 8 + 4);
        float c0 = __cosf(v0.x + th[0]);
        float c1 = __cosf(v0.y + th[1]);
        float c2 = __cosf(v0.z + th[2]);
        float c3 = __cosf(v0.w + th[3]);
        float c4 = __cosf(v1.x + th[4]);
        float c5 = __cosf(v1.y + th[5]);
        float c6 = __cosf(v1.z + th[6]);
        float c7 = __cosf(v1.w + th[7]);
        uint4 up, us;
        up.x = cvt_f16x2(c1, c0); up.y = cvt_f16x2(c3, c2);
        up.z = cvt_f16x2(c5, c4); up.w = cvt_f16x2(c7, c6);
        us.x = cvt_f16x2(c1 * SCALE_F, c0 * SCALE_F);
        us.y = cvt_f16x2(c3 * SCALE_F, c2 * SCALE_F);
        us.z = cvt_f16x2(c5 * SCALE_F, c4 * SCALE_F);
        us.w = cvt_f16x2(c7 * SCALE_F, c6 * SCALE_F);
        *(uint4*)(P + row * 8)  = up;
        *(uint4*)(Ps + row * 8) = us;
    }
    __syncwarp();

    uint32_t pA0 = smem_u32(Ps + lane * 8);
    uint32_t pA1 = smem_u32(Ps + (lane + 32) * 8);
    uint32_t pB0 = smem_u32(P + lane * 8);
    uint32_t pB1 = smem_u32(P + (lane + 32) * 8);
    uint32_t a[8], b1[8], bt[8];
    ldsm4(a, pA0);      ldsm4(a + 4, pA1);
    ldsm4(b1, pB0);     ldsm4(b1 + 4, pB1);
    ldsm4t(bt, pB0);    ldsm4t(bt + 4, pB1);

    int b = token >> 11;
    int s = token & 2047;
    int g = lane >> 2, t = lane & 3;
    size_t obase = ((size_t)b << 20) + ((size_t)s << 3) + 2 * t;

#pragma unroll
    for (int mi = 0; mi < 4; mi++) {
        float D[8][4];
#pragma unroll
        for (int ni = 0; ni < 8; ni++) {
            D[ni][0] = 0.f; D[ni][1] = 0.f; D[ni][2] = 0.f; D[ni][3] = 0.f;
            mma_k8(D[ni], &a[2 * mi], b1[ni]);
        }
        float lg = 0.f, lg8 = 0.f;
        uint32_t slo[8], shi[8];
#pragma unroll
        for (int ni = 0; ni < 8; ni++) {
            float e0 = ex2f(D[ni][0]);
            float e1 = ex2f(D[ni][1]);
            float e2 = ex2f(D[ni][2]);
            float e3 = ex2f(D[ni][3]);
            lg  += e0 + e1;
            lg8 += e2 + e3;
            slo[ni] = cvt_f16x2(e1, e0);
            shi[ni] = cvt_f16x2(e3, e2);
        }
        lg  += __shfl_xor_sync(0xffffffffu, lg, 1);
        lg  += __shfl_xor_sync(0xffffffffu, lg, 2);
        lg8 += __shfl_xor_sync(0xffffffffu, lg8, 1);
        lg8 += __shfl_xor_sync(0xffffffffu, lg8, 2);

        float o[4] = {0.f, 0.f, 0.f, 0.f};
#pragma unroll
        for (int kb = 0; kb < 4; kb++) {
            uint32_t af[4] = { slo[2 * kb], shi[2 * kb],
                               slo[2 * kb + 1], shi[2 * kb + 1] };
            mma16(o, af, &bt[2 * kb]);
        }
        float ig = 1.0f / lg, ig8 = 1.0f / lg8;

        int h0 = 16 * mi + g;
        uint32_t r0 = cvt_f16x2(o[1] * ig, o[0] * ig);
        uint32_t r1 = cvt_f16x2(o[3] * ig8, o[2] * ig8);
        *(uint32_t*)(g_scratch + obase + ((size_t)h0 << 14)) = r0;
        *(uint32_t*)(g_scratch + obase + ((size_t)(h0 + 8) << 14)) = r1;
    }
}

// ---------------------------------------------------------------------------
// Kernel 2: C[16384,512] = scratch @ W^T + bias, fp16 mma m16n8k16 (f32 acc).
// Block tile 128x128, 4 warps (2x2), warp tile 64x64 (128 acc regs).
// BK=16, 5-stage cp.async pipeline (12KB/stage, 60KB total) with 4 stages
// in flight (wait_group 4 + empty-group commits at the tail).
// ROWW=12 padded rows: conflict-free for both 16B async stores
// (banks 12t / 12t+4 distinct per phase) and ldmatrix
// ({12r mod 32} = {0,12,24,4,16,28,8,20}, all = 0 mod 4, tiles all banks).
// ---------------------------------------------------------------------------
#define ROWW 12                    // words per padded 8-word (16-half) row
#define STAGE_WORDS (256 * ROWW)   // A(128 rows) + B(128 rows) = 3072 words
#define NSTAGE 5
#define GEMM_SMEM (NSTAGE * STAGE_WORDS * 4)   // 61440 bytes
#define NKT 32                     // 512 / 16

__global__ void __launch_bounds__(128, 3) gemm_kernel(
    const float* __restrict__ bias,   // [512]
    float* __restrict__ C)            // [16384][512]
{
    extern __shared__ __align__(16) uint32_t sm[];
    const __half* A = g_scratch;
    const __half* B = g_Whf;

    int tid  = threadIdx.x;
    int warp = tid >> 5, lane = tid & 31;
    int wm = warp >> 1, wn = warp & 1;     // 2 x 2 warp grid, warp tile 64x64
    int bm = blockIdx.y, bn = blockIdx.x;

    float c[4][8][4];                      // [mi][ni][frag]: 128 regs
#pragma unroll
    for (int mi = 0; mi < 4; mi++)
#pragma unroll
        for (int ni = 0; ni < 8; ni++)
#pragma unroll
            for (int k = 0; k < 4; k++) c[mi][ni][k] = 0.f;

    uint32_t smb = (uint32_t)__cvta_generic_to_shared(sm);
    const __half* gA = A + (size_t)(bm * 128) * 512 + (size_t)tid * 512;
    const __half* gB = B + (size_t)(bn * 128) * 512 + (size_t)tid * 512;

    // Staging: thread t owns row t of A and row t of B (2 x 16B chunks each).
    uint32_t stA0 = smb + (uint32_t)(tid * ROWW) * 4;
    uint32_t stB0 = smb + (uint32_t)((128 + tid) * ROWW) * 4;

    auto produce = [&](int kt, int s) {
        uint32_t so = (uint32_t)s * (STAGE_WORDS * 4);
        int kc = kt * 16;
        cp_async16(stA0 + so,      gA + kc);
        cp_async16(stA0 + so + 16, gA + kc + 8);
        cp_async16(stB0 + so,      gB + kc);
        cp_async16(stB0 + so + 16, gB + kc + 8);
        CP_COMMIT();
    };

    produce(0, 0);
    produce(1, 1);
    produce(2, 2);
    produce(3, 3);

    // ldmatrix bases. A x4 for mi: row = wm*64+mi*16+(j&1)*8+(lane&7),
    // kword = (lane>>4)*4.  B x4 for p: row = 128+wn*64+p*16+(j>>1)*8+
    // (lane&7), kword = (j&1)*4; yields n-chunks 2p, 2p+1.
    int j = lane >> 3;
    uint32_t aAddr0 = smb
        + ((uint32_t)((wm * 64 + (j & 1) * 8 + (lane & 7)) * ROWW + (lane >> 4) * 4)) * 4;
    uint32_t bAddr0 = smb
        + ((uint32_t)((128 + wn * 64 + (j >> 1) * 8 + (lane & 7)) * ROWW + (j & 1) * 4)) * 4;

    int s = 0, sp = 4 % NSTAGE;
    for (int kt = 0; kt < NKT; kt++) {
        __syncthreads();                       // stage sp is free to overwrite
        if (kt + 4 < NKT) produce(kt + 4, sp); // keep queue full...
        else CP_COMMIT();                      // ...or pad with empty group
        CP_WAIT(4);                            // stage s (oldest) is ready

        uint32_t sOff = (uint32_t)s * (STAGE_WORDS * 4);
        uint32_t af[4][4];
#pragma unroll
        for (int mi = 0; mi < 4; mi++)
            ldsm4(af[mi], aAddr0 + sOff + (uint32_t)(mi * 16 * ROWW) * 4);
#pragma unroll
        for (int p = 0; p < 4; p++) {
            uint32_t r[4];
            ldsm4(r, bAddr0 + sOff + (uint32_t)(p * 16 * ROWW) * 4);
#pragma unroll
            for (int mi = 0; mi < 4; mi++) {
                mma16(c[mi][2 * p],     af[mi], r);
                mma16(c[mi][2 * p + 1], af[mi], r + 2);
            }
        }
        s = (s + 1 == NSTAGE) ? 0 : s + 1;
        sp = (sp + 1 == NSTAGE) ? 0 : sp + 1;
    }

    // Epilogue: C = acc + bias
    int g = lane >> 2, t = lane & 3;
#pragma unroll
    for (int mi = 0; mi < 4; mi++) {
        int row = bm * 128 + wm * 64 + mi * 16 + g;
#pragma unroll
        for (int ni = 0; ni < 8; ni++) {
            int col = bn * 128 + wn * 64 + ni * 8 + 2 * t;
            float2 bv = *(const float2*)&bias[col];
            *(float2*)&C[(size_t)row * 512 + col] =
                make_float2(c[mi][ni][0] + bv.x, c[mi][ni][1] + bv.y);
            *(float2*)&C[(size_t)(row + 8) * 512 + col] =
                make_float2(c[mi][ni][2] + bv.x, c[mi][ni][3] + bv.y);
        }
    }
}

// ---------------------------------------------------------------------------
extern "C" void kernel_launch(void* const* d_in, const int* in_sizes, int n_in,
                              void* d_out, int out_size)
{
    const float* x     = (const float*)d_in[0];
    const float* theta = (const float*)d_in[1];
    const float* Wm    = (const float*)d_in[2];
    const float* bias  = (const float*)d_in[3];
    float* out = (float*)d_out;

    cudaFuncSetAttribute(gemm_kernel,
                         cudaFuncAttributeMaxDynamicSharedMemorySize, GEMM_SMEM);

    attn_kernel<<<M_TOTAL / 8, 256>>>(x, theta, Wm);

    dim3 grid(4, 128);  // (N tiles, M tiles)
    gemm_kernel<<<grid, 128, GEMM_SMEM>>>(bias, out);
}